// round 1
// baseline (speedup 1.0000x reference)
#include <cuda_runtime.h>
#include <math.h>

#define B_   8
#define T_   22050
#define NCH  31
#define BN   (B_*NCH)
#define M_   12
#define LG   2048
#define LH   512

// ---------------- device scratch (static, no runtime alloc) ----------------
__device__ float g_hpme[1024];          // hp (x) me combined FIR (1023 taps + 1 zero pad)
__device__ float g_wlp[256];            // 5x cascaded one-pole LP as truncated FIR
__device__ int   g_keff[NCH];           // per-channel effective gammatone length
__device__ float g_y1[B_*T_];           // after hp+me
__device__ float g_hw[BN*T_];           // rectified gammatone output
__device__ float g_env[BN*T_];          // IHC envelope

// ---------------- prep kernels ----------------
__global__ void hpme_kernel(const float* __restrict__ hp, const float* __restrict__ me) {
    int j = threadIdx.x;
    float s = 0.f;
    if (j < 1023) {
        int mlo = j - 511; if (mlo < 0) mlo = 0;
        int mhi = j; if (mhi > 511) mhi = 511;
        for (int m = mlo; m <= mhi; ++m) s += hp[m] * me[j - m];
    }
    g_hpme[j] = s;
}

__global__ void wlp_kernel() {
    int k = threadIdx.x;
    // reference uses a_lp rounded to f32; replicate that then expand in double
    double a = (double)(float)exp(-2.0 * M_PI * 2000.0 / 44100.0);
    double c = ((double)(k + 1) * (double)(k + 2) * (double)(k + 3) * (double)(k + 4)) / 24.0;
    double w = pow(1.0 - a, 5.0) * c * exp((double)k * log(a));
    g_wlp[k] = (float)w;
}

__global__ void keff_kernel(const float* __restrict__ gt) {
    int n = threadIdx.x;
    if (n >= NCH) return;
    const float* h = gt + n * LG;
    float mx = 0.f;
    for (int k = 0; k < LG; ++k) mx = fmaxf(mx, fabsf(h[k]));
    float thr = 1e-6f * mx;
    int last = 0;
    for (int k = 0; k < LG; ++k) if (fabsf(h[k]) > thr) last = k;
    int K = ((last + 1 + 7) / 8) * 8;
    if (K < 8) K = 8;
    if (K > LG) K = LG;
    g_keff[n] = K;
}

// ---------------- generic register-blocked causal FIR conv ----------------
// out[t] = sum_{k<K} h[k] * in[t-k] ; each thread computes 8 consecutive t.
__global__ __launch_bounds__(128) void conv1d_kernel(const float* __restrict__ xin,
                                                     const float* __restrict__ gtin,
                                                     int mode) {
    __shared__ __align__(16) float hr[2048];
    __shared__ __align__(16) float xs[2048 + 1024 + 16];

    int tid = threadIdx.x;
    int t0 = blockIdx.x * 1024;
    int row = blockIdx.y;

    const float* in; const float* hsrc; float* out; int K; bool relu = false;
    if (mode == 0) {                     // x -> y1  (hp*me, 1023 taps padded to 1024)
        in = xin + (size_t)row * T_; hsrc = g_hpme; K = 1024;
        out = g_y1 + (size_t)row * T_;
    } else if (mode == 1) {              // y1 -> hw (gammatone + rectify, truncated)
        int b = row / NCH, n = row % NCH;
        in = g_y1 + (size_t)b * T_; hsrc = gtin + (size_t)n * LG; K = g_keff[n];
        out = g_hw + (size_t)row * T_; relu = true;
    } else {                             // hw -> env (IHC LP as 256-tap FIR)
        in = g_hw + (size_t)row * T_; hsrc = g_wlp; K = 256;
        out = g_env + (size_t)row * T_;
    }

    for (int i = tid; i < K; i += 128) hr[i] = hsrc[K - 1 - i];   // reversed filter
    int xlen = K - 1 + 1024;
    for (int i = tid; i < xlen; i += 128) {
        int t = t0 - (K - 1) + i;
        xs[i] = (t >= 0 && t < T_) ? in[t] : 0.f;
    }
    __syncthreads();

    float acc[8];
#pragma unroll
    for (int r = 0; r < 8; ++r) acc[r] = 0.f;
    int off = tid * 8;

    for (int k = 0; k < K; k += 8) {
        float4 h0 = *reinterpret_cast<const float4*>(hr + k);
        float4 h1 = *reinterpret_cast<const float4*>(hr + k + 4);
        const float* xp = xs + off + k;
        float4 x0 = *reinterpret_cast<const float4*>(xp);
        float4 x1 = *reinterpret_cast<const float4*>(xp + 4);
        float4 x2 = *reinterpret_cast<const float4*>(xp + 8);
        float4 x3 = *reinterpret_cast<const float4*>(xp + 12);
        float hk[8] = {h0.x, h0.y, h0.z, h0.w, h1.x, h1.y, h1.z, h1.w};
        float xw[16] = {x0.x, x0.y, x0.z, x0.w, x1.x, x1.y, x1.z, x1.w,
                        x2.x, x2.y, x2.z, x2.w, x3.x, x3.y, x3.z, x3.w};
#pragma unroll
        for (int kk = 0; kk < 8; ++kk)
#pragma unroll
            for (int r = 0; r < 8; ++r)
                acc[r] = fmaf(hk[kk], xw[kk + r], acc[r]);
    }

#pragma unroll
    for (int r = 0; r < 8; ++r) {
        int t = t0 + off + r;
        if (t < T_) out[t] = relu ? fmaxf(acc[r], 0.f) : acc[r];
    }
}

// ---------------- adaptation + modulation: wavefront-pipelined warp ----------------
struct AMConst {
    float a1[5], b0[5], fac[5], efac[5], off[5], ini[5];
    float corr, scale, att, minlvl;
    float pre[12], pim[12], pb0[12];
};

__global__ __launch_bounds__(32) void adapt_mod_kernel(float* __restrict__ out, AMConst C) {
    const unsigned FULL = 0xffffffffu;
    int c = blockIdx.x;                  // channel (b*31+n), 0..247
    int lane = threadIdx.x;
    const float* __restrict__ erow = g_env + (size_t)c * T_;
    float* __restrict__ orow = out + (size_t)c * (M_ * T_);

    bool isAd = lane < 5;
    bool isMod = (lane >= 5) && (lane < 5 + M_);
    int j = isAd ? lane : 0;
    int m = isMod ? (lane - 5) : 0;

    float a1 = C.a1[j], b0 = C.b0[j], fac = C.fac[j], efac = C.efac[j], offc = C.off[j];
    float st = C.ini[j];
    float rst = __fdividef(1.0f, st);

    float pre = C.pre[m], pim = C.pim[m], pb0 = C.pb0[m];
    bool low = (m < 3);                  // mfc <= 10 Hz -> real part
    float sre = 0.f, sim = 0.f;

    float tmp_out = 0.f;

    // 32-wide coalesced env prefetch, one block ahead
    float ebuf  = erow[lane];
    float ebufn = (32 + lane < T_) ? erow[32 + lane] : 0.f;

    const int NIT = T_ + 5;
    for (int i = 0; i < NIT; ++i) {
        float prev = __shfl_up_sync(FULL, tmp_out, 1);   // stage j-1 output at t=i-j
        float adv  = __shfl_sync(FULL, tmp_out, 4);      // adaptation output at t=i-5
        float envv = __shfl_sync(FULL, ebuf, i & 31);
        if ((i & 31) == 31) {
            ebuf = ebufn;
            int nidx = i + 1 + 32 + lane;
            ebufn = (nidx < T_) ? erow[nidx] : 0.f;
        }

        // ---- one adaptation loop stage ----
        float tin = (lane == 0) ? fmaxf(envv, C.minlvl) : prev;
        float t1  = tin * rst;
        float e   = __expf(efac * (t1 - 1.0f));
        float lim = __fdividef(fac, 1.0f + e) - offc;
        float to  = (t1 > 1.0f) ? lim : t1;

        int tj = i - lane;
        if (isAd && (unsigned)tj < (unsigned)T_) {
            st = fmaf(a1, st, b0 * to);
            rst = __fdividef(1.0f, st);
            tmp_out = to;
        }

        // ---- modulation resonators (one pipeline stage later) ----
        int tm = i - 5;
        if (isMod && (unsigned)tm < (unsigned)T_) {
            float x   = (adv - C.corr) * C.scale;
            float nre = fmaf(pre, sre, fmaf(-pim, sim, pb0 * x));
            float nim = fmaf(pre, sim, pim * sre);
            sre = nre; sim = nim;
            float o = low ? nre
                          : C.att * sqrtf(fmaf(nre, nre, fmaf(nim, nim, 1e-12f)));
            orow[(size_t)m * T_ + tm] = o;
        }
    }
}

// ---------------- host launch ----------------
extern "C" void kernel_launch(void* const* d_in, const int* in_sizes, int n_in,
                              void* d_out, int out_size) {
    const float* x  = (const float*)d_in[0];
    const float* hp = (const float*)d_in[1];
    const float* me = (const float*)d_in[2];
    const float* gt = (const float*)d_in[3];
    float* out = (float*)d_out;
    (void)in_sizes; (void)n_in; (void)out_size;

    AMConst C;
    const double taus[5] = {0.005, 0.05, 0.129, 0.253, 0.5};
    for (int j = 0; j < 5; ++j) {
        double a1d = exp(-1.0 / (44100.0 * taus[j]));
        float a1f = (float)a1d;
        C.a1[j] = a1f;
        C.b0[j] = 1.0f - a1f;
        double ini = pow(1e-5, pow(2.0, -(double)(j + 1)));
        float inif = (float)ini;
        C.ini[j] = inif;
        double maxv = (1.0 - (double)inif * (double)inif) * 5.0 - 1.0;
        C.fac[j]  = (float)(2.0 * maxv);
        C.efac[j] = (float)(-2.0 / maxv);
        C.off[j]  = (float)(maxv - 1.0);
    }
    double corr = pow(1e-5, 1.0 / 32.0);
    C.corr   = (float)corr;
    C.scale  = (float)(100.0 / (1.0 - corr));
    C.att    = (float)(1.0 / sqrt(2.0));
    C.minlvl = 1e-5f;

    const float mfcf[12] = {2.5f, 5.0f, 10.0f, 16.7f, 27.8f, 46.3f, 77.2f,
                            128.6f, 214.3f, 357.2f, 595.4f, 992.3f};
    for (int m = 0; m < 12; ++m) {
        double mv = (double)mfcf[m];
        double r  = exp(-M_PI * (mv / 2.0) / 44100.0);
        double th = 2.0 * M_PI * mv / 44100.0;
        C.pre[m] = (float)(r * cos(th));
        C.pim[m] = (float)(r * sin(th));
        C.pb0[m] = (float)(1.0 - r);
    }

    hpme_kernel<<<1, 1024>>>(hp, me);
    wlp_kernel<<<1, 256>>>();
    keff_kernel<<<1, 32>>>(gt);

    dim3 blk(128);
    conv1d_kernel<<<dim3(22, B_), blk>>>(x, gt, 0);   // hp+me
    conv1d_kernel<<<dim3(22, BN), blk>>>(x, gt, 1);   // gammatone + rectify
    conv1d_kernel<<<dim3(22, BN), blk>>>(x, gt, 2);   // IHC LP (FIR)

    adapt_mod_kernel<<<BN, 32>>>(out, C);
}

// round 2
// speedup vs baseline: 1.0005x; 1.0005x over previous
#include <cuda_runtime.h>
#include <math.h>

#define B_   8
#define T_   22050
#define NCH  31
#define BN   (B_*NCH)
#define M_   12
#define LG   2048
#define LH   512

// ---------------- device scratch (static, no runtime alloc) ----------------
__device__ float g_hpme[1024];          // hp (x) me combined FIR (1023 taps + 1 zero pad)
__device__ float g_wlp[256];            // 5x cascaded one-pole LP as truncated FIR
__device__ int   g_keff[NCH];           // per-channel effective gammatone length
__device__ float g_y1[B_*T_];           // after hp+me
__device__ float g_hw[BN*T_];           // rectified gammatone output
__device__ float g_env[BN*T_];          // IHC envelope

// ---------------- prep kernels ----------------
__global__ void hpme_kernel(const float* __restrict__ hp, const float* __restrict__ me) {
    int j = threadIdx.x;
    float s = 0.f;
    if (j < 1023) {
        int mlo = j - 511; if (mlo < 0) mlo = 0;
        int mhi = j; if (mhi > 511) mhi = 511;
        for (int m = mlo; m <= mhi; ++m) s += hp[m] * me[j - m];
    }
    g_hpme[j] = s;
}

__global__ void wlp_kernel() {
    int k = threadIdx.x;
    // reference uses a_lp rounded to f32; replicate that then expand in double
    double a = (double)(float)exp(-2.0 * M_PI * 2000.0 / 44100.0);
    double c = ((double)(k + 1) * (double)(k + 2) * (double)(k + 3) * (double)(k + 4)) / 24.0;
    double w = pow(1.0 - a, 5.0) * c * exp((double)k * log(a));
    g_wlp[k] = (float)w;
}

__global__ void keff_kernel(const float* __restrict__ gt) {
    int n = threadIdx.x;
    if (n >= NCH) return;
    const float* h = gt + n * LG;
    float mx = 0.f;
    for (int k = 0; k < LG; ++k) mx = fmaxf(mx, fabsf(h[k]));
    float thr = 1e-6f * mx;
    int last = 0;
    for (int k = 0; k < LG; ++k) if (fabsf(h[k]) > thr) last = k;
    int K = ((last + 1 + 7) / 8) * 8;
    if (K < 8) K = 8;
    if (K > LG) K = LG;
    g_keff[n] = K;
}

// ---------------- generic register-blocked causal FIR conv ----------------
// out[t] = sum_{k<K} h[k] * in[t-k] ; each thread computes 8 consecutive t.
__global__ __launch_bounds__(128) void conv1d_kernel(const float* __restrict__ xin,
                                                     const float* __restrict__ gtin,
                                                     int mode) {
    __shared__ __align__(16) float hr[2048];
    __shared__ __align__(16) float xs[2048 + 1024 + 16];

    int tid = threadIdx.x;
    int t0 = blockIdx.x * 1024;
    int row = blockIdx.y;

    const float* in; const float* hsrc; float* out; int K; bool relu = false;
    if (mode == 0) {                     // x -> y1  (hp*me, 1023 taps padded to 1024)
        in = xin + (size_t)row * T_; hsrc = g_hpme; K = 1024;
        out = g_y1 + (size_t)row * T_;
    } else if (mode == 1) {              // y1 -> hw (gammatone + rectify, truncated)
        int b = row / NCH, n = row % NCH;
        in = g_y1 + (size_t)b * T_; hsrc = gtin + (size_t)n * LG; K = g_keff[n];
        out = g_hw + (size_t)row * T_; relu = true;
    } else {                             // hw -> env (IHC LP as 256-tap FIR)
        in = g_hw + (size_t)row * T_; hsrc = g_wlp; K = 256;
        out = g_env + (size_t)row * T_;
    }

    for (int i = tid; i < K; i += 128) hr[i] = hsrc[K - 1 - i];   // reversed filter
    int xlen = K - 1 + 1024;
    for (int i = tid; i < xlen; i += 128) {
        int t = t0 - (K - 1) + i;
        xs[i] = (t >= 0 && t < T_) ? in[t] : 0.f;
    }
    __syncthreads();

    float acc[8];
#pragma unroll
    for (int r = 0; r < 8; ++r) acc[r] = 0.f;
    int off = tid * 8;

    for (int k = 0; k < K; k += 8) {
        float4 h0 = *reinterpret_cast<const float4*>(hr + k);
        float4 h1 = *reinterpret_cast<const float4*>(hr + k + 4);
        const float* xp = xs + off + k;
        float4 x0 = *reinterpret_cast<const float4*>(xp);
        float4 x1 = *reinterpret_cast<const float4*>(xp + 4);
        float4 x2 = *reinterpret_cast<const float4*>(xp + 8);
        float4 x3 = *reinterpret_cast<const float4*>(xp + 12);
        float hk[8] = {h0.x, h0.y, h0.z, h0.w, h1.x, h1.y, h1.z, h1.w};
        float xw[16] = {x0.x, x0.y, x0.z, x0.w, x1.x, x1.y, x1.z, x1.w,
                        x2.x, x2.y, x2.z, x2.w, x3.x, x3.y, x3.z, x3.w};
#pragma unroll
        for (int kk = 0; kk < 8; ++kk)
#pragma unroll
            for (int r = 0; r < 8; ++r)
                acc[r] = fmaf(hk[kk], xw[kk + r], acc[r]);
    }

#pragma unroll
    for (int r = 0; r < 8; ++r) {
        int t = t0 + off + r;
        if (t < T_) out[t] = relu ? fmaxf(acc[r], 0.f) : acc[r];
    }
}

// ---------------- adaptation + modulation: wavefront-pipelined warp ----------------
struct AMConst {
    float a1[5], b0[5], fac[5], efac[5], off[5], ini[5];
    float corr, scale, att, minlvl;
    float pre[12], pim[12], pb0[12];
};

__global__ __launch_bounds__(32) void adapt_mod_kernel(float* __restrict__ out, AMConst C) {
    const unsigned FULL = 0xffffffffu;
    int c = blockIdx.x;                  // channel (b*31+n), 0..247
    int lane = threadIdx.x;
    const float* __restrict__ erow = g_env + (size_t)c * T_;
    float* __restrict__ orow = out + (size_t)c * (M_ * T_);

    bool isAd = lane < 5;
    bool isMod = (lane >= 5) && (lane < 5 + M_);
    int j = isAd ? lane : 0;
    int m = isMod ? (lane - 5) : 0;

    float a1 = C.a1[j], b0 = C.b0[j], fac = C.fac[j], efac = C.efac[j], offc = C.off[j];
    float st = C.ini[j];
    float rst = __fdividef(1.0f, st);

    float pre = C.pre[m], pim = C.pim[m], pb0 = C.pb0[m];
    bool low = (m < 3);                  // mfc <= 10 Hz -> real part
    float sre = 0.f, sim = 0.f;

    float tmp_out = 0.f;

    // 32-wide coalesced env prefetch, one block ahead
    float ebuf  = erow[lane];
    float ebufn = (32 + lane < T_) ? erow[32 + lane] : 0.f;

    const int NIT = T_ + 5;
    for (int i = 0; i < NIT; ++i) {
        float prev = __shfl_up_sync(FULL, tmp_out, 1);   // stage j-1 output at t=i-j
        float adv  = __shfl_sync(FULL, tmp_out, 4);      // adaptation output at t=i-5
        float envv = __shfl_sync(FULL, ebuf, i & 31);
        if ((i & 31) == 31) {
            ebuf = ebufn;
            int nidx = i + 1 + 32 + lane;
            ebufn = (nidx < T_) ? erow[nidx] : 0.f;
        }

        // ---- one adaptation loop stage ----
        float tin = (lane == 0) ? fmaxf(envv, C.minlvl) : prev;
        float t1  = tin * rst;
        float e   = __expf(efac * (t1 - 1.0f));
        float lim = __fdividef(fac, 1.0f + e) - offc;
        float to  = (t1 > 1.0f) ? lim : t1;

        int tj = i - lane;
        if (isAd && (unsigned)tj < (unsigned)T_) {
            st = fmaf(a1, st, b0 * to);
            rst = __fdividef(1.0f, st);
            tmp_out = to;
        }

        // ---- modulation resonators (one pipeline stage later) ----
        int tm = i - 5;
        if (isMod && (unsigned)tm < (unsigned)T_) {
            float x   = (adv - C.corr) * C.scale;
            float nre = fmaf(pre, sre, fmaf(-pim, sim, pb0 * x));
            float nim = fmaf(pre, sim, pim * sre);
            sre = nre; sim = nim;
            float o = low ? nre
                          : C.att * sqrtf(fmaf(nre, nre, fmaf(nim, nim, 1e-12f)));
            orow[(size_t)m * T_ + tm] = o;
        }
    }
}

// ---------------- host launch ----------------
extern "C" void kernel_launch(void* const* d_in, const int* in_sizes, int n_in,
                              void* d_out, int out_size) {
    const float* x  = (const float*)d_in[0];
    const float* hp = (const float*)d_in[1];
    const float* me = (const float*)d_in[2];
    const float* gt = (const float*)d_in[3];
    float* out = (float*)d_out;
    (void)in_sizes; (void)n_in; (void)out_size;

    AMConst C;
    const double taus[5] = {0.005, 0.05, 0.129, 0.253, 0.5};
    for (int j = 0; j < 5; ++j) {
        double a1d = exp(-1.0 / (44100.0 * taus[j]));
        float a1f = (float)a1d;
        C.a1[j] = a1f;
        C.b0[j] = 1.0f - a1f;
        double ini = pow(1e-5, pow(2.0, -(double)(j + 1)));
        float inif = (float)ini;
        C.ini[j] = inif;
        double maxv = (1.0 - (double)inif * (double)inif) * 5.0 - 1.0;
        C.fac[j]  = (float)(2.0 * maxv);
        C.efac[j] = (float)(-2.0 / maxv);
        C.off[j]  = (float)(maxv - 1.0);
    }
    double corr = pow(1e-5, 1.0 / 32.0);
    C.corr   = (float)corr;
    C.scale  = (float)(100.0 / (1.0 - corr));
    C.att    = (float)(1.0 / sqrt(2.0));
    C.minlvl = 1e-5f;

    const float mfcf[12] = {2.5f, 5.0f, 10.0f, 16.7f, 27.8f, 46.3f, 77.2f,
                            128.6f, 214.3f, 357.2f, 595.4f, 992.3f};
    for (int m = 0; m < 12; ++m) {
        double mv = (double)mfcf[m];
        double r  = exp(-M_PI * (mv / 2.0) / 44100.0);
        double th = 2.0 * M_PI * mv / 44100.0;
        C.pre[m] = (float)(r * cos(th));
        C.pim[m] = (float)(r * sin(th));
        C.pb0[m] = (float)(1.0 - r);
    }

    hpme_kernel<<<1, 1024>>>(hp, me);
    wlp_kernel<<<1, 256>>>();
    keff_kernel<<<1, 32>>>(gt);

    dim3 blk(128);
    conv1d_kernel<<<dim3(22, B_), blk>>>(x, gt, 0);   // hp+me
    conv1d_kernel<<<dim3(22, BN), blk>>>(x, gt, 1);   // gammatone + rectify
    conv1d_kernel<<<dim3(22, BN), blk>>>(x, gt, 2);   // IHC LP (FIR)

    adapt_mod_kernel<<<BN, 32>>>(out, C);
}

// round 3
// speedup vs baseline: 1.0006x; 1.0002x over previous
#include <cuda_runtime.h>
#include <math.h>

#define B_   8
#define T_   22050
#define NCH  31
#define BN   (B_*NCH)
#define M_   12
#define LG   2048
#define LH   512

// ---------------- device scratch (static, no runtime alloc) ----------------
__device__ float g_hpme[1024];          // hp (x) me combined FIR (1023 taps + 1 zero pad)
__device__ float g_wlp[256];            // 5x cascaded one-pole LP as truncated FIR
__device__ int   g_keff[NCH];           // per-channel effective gammatone length
__device__ float g_y1[B_*T_];           // after hp+me
__device__ float g_hw[BN*T_];           // rectified gammatone output
__device__ float g_env[BN*T_];          // IHC envelope

// ---------------- prep kernels ----------------
__global__ void hpme_kernel(const float* __restrict__ hp, const float* __restrict__ me) {
    int j = threadIdx.x;
    float s = 0.f;
    if (j < 1023) {
        int mlo = j - 511; if (mlo < 0) mlo = 0;
        int mhi = j; if (mhi > 511) mhi = 511;
        for (int m = mlo; m <= mhi; ++m) s += hp[m] * me[j - m];
    }
    g_hpme[j] = s;
}

__global__ void wlp_kernel() {
    int k = threadIdx.x;
    // reference uses a_lp rounded to f32; replicate that then expand in double
    double a = (double)(float)exp(-2.0 * M_PI * 2000.0 / 44100.0);
    double c = ((double)(k + 1) * (double)(k + 2) * (double)(k + 3) * (double)(k + 4)) / 24.0;
    double w = pow(1.0 - a, 5.0) * c * exp((double)k * log(a));
    g_wlp[k] = (float)w;
}

__global__ void keff_kernel(const float* __restrict__ gt) {
    int n = threadIdx.x;
    if (n >= NCH) return;
    const float* h = gt + n * LG;
    float mx = 0.f;
    for (int k = 0; k < LG; ++k) mx = fmaxf(mx, fabsf(h[k]));
    float thr = 1e-6f * mx;
    int last = 0;
    for (int k = 0; k < LG; ++k) if (fabsf(h[k]) > thr) last = k;
    int K = ((last + 1 + 7) / 8) * 8;
    if (K < 8) K = 8;
    if (K > LG) K = LG;
    g_keff[n] = K;
}

// ---------------- generic register-blocked causal FIR conv ----------------
// out[t] = sum_{k<K} h[k] * in[t-k] ; each thread computes 8 consecutive t.
__global__ __launch_bounds__(128) void conv1d_kernel(const float* __restrict__ xin,
                                                     const float* __restrict__ gtin,
                                                     int mode) {
    __shared__ __align__(16) float hr[2048];
    __shared__ __align__(16) float xs[2048 + 1024 + 16];

    int tid = threadIdx.x;
    int t0 = blockIdx.x * 1024;
    int row = blockIdx.y;

    const float* in; const float* hsrc; float* out; int K; bool relu = false;
    if (mode == 0) {                     // x -> y1  (hp*me, 1023 taps padded to 1024)
        in = xin + (size_t)row * T_; hsrc = g_hpme; K = 1024;
        out = g_y1 + (size_t)row * T_;
    } else if (mode == 1) {              // y1 -> hw (gammatone + rectify, truncated)
        int b = row / NCH, n = row % NCH;
        in = g_y1 + (size_t)b * T_; hsrc = gtin + (size_t)n * LG; K = g_keff[n];
        out = g_hw + (size_t)row * T_; relu = true;
    } else {                             // hw -> env (IHC LP as 256-tap FIR)
        in = g_hw + (size_t)row * T_; hsrc = g_wlp; K = 256;
        out = g_env + (size_t)row * T_;
    }

    for (int i = tid; i < K; i += 128) hr[i] = hsrc[K - 1 - i];   // reversed filter
    int xlen = K - 1 + 1024;
    for (int i = tid; i < xlen; i += 128) {
        int t = t0 - (K - 1) + i;
        xs[i] = (t >= 0 && t < T_) ? in[t] : 0.f;
    }
    __syncthreads();

    float acc[8];
#pragma unroll
    for (int r = 0; r < 8; ++r) acc[r] = 0.f;
    int off = tid * 8;

    for (int k = 0; k < K; k += 8) {
        float4 h0 = *reinterpret_cast<const float4*>(hr + k);
        float4 h1 = *reinterpret_cast<const float4*>(hr + k + 4);
        const float* xp = xs + off + k;
        float4 x0 = *reinterpret_cast<const float4*>(xp);
        float4 x1 = *reinterpret_cast<const float4*>(xp + 4);
        float4 x2 = *reinterpret_cast<const float4*>(xp + 8);
        float4 x3 = *reinterpret_cast<const float4*>(xp + 12);
        float hk[8] = {h0.x, h0.y, h0.z, h0.w, h1.x, h1.y, h1.z, h1.w};
        float xw[16] = {x0.x, x0.y, x0.z, x0.w, x1.x, x1.y, x1.z, x1.w,
                        x2.x, x2.y, x2.z, x2.w, x3.x, x3.y, x3.z, x3.w};
#pragma unroll
        for (int kk = 0; kk < 8; ++kk)
#pragma unroll
            for (int r = 0; r < 8; ++r)
                acc[r] = fmaf(hk[kk], xw[kk + r], acc[r]);
    }

#pragma unroll
    for (int r = 0; r < 8; ++r) {
        int t = t0 + off + r;
        if (t < T_) out[t] = relu ? fmaxf(acc[r], 0.f) : acc[r];
    }
}

// ---------------- adaptation + modulation: wavefront-pipelined warp ----------------
struct AMConst {
    float a1[5], b0[5], fac[5], efac[5], off[5], ini[5];
    float corr, scale, att, minlvl;
    float pre[12], pim[12], pb0[12];
};

__global__ __launch_bounds__(32) void adapt_mod_kernel(float* __restrict__ out, AMConst C) {
    const unsigned FULL = 0xffffffffu;
    int c = blockIdx.x;                  // channel (b*31+n), 0..247
    int lane = threadIdx.x;
    const float* __restrict__ erow = g_env + (size_t)c * T_;
    float* __restrict__ orow = out + (size_t)c * (M_ * T_);

    bool isAd = lane < 5;
    bool isMod = (lane >= 5) && (lane < 5 + M_);
    int j = isAd ? lane : 0;
    int m = isMod ? (lane - 5) : 0;

    float a1 = C.a1[j], b0 = C.b0[j], fac = C.fac[j], efac = C.efac[j], offc = C.off[j];
    float st = C.ini[j];
    float rst = __fdividef(1.0f, st);

    float pre = C.pre[m], pim = C.pim[m], pb0 = C.pb0[m];
    bool low = (m < 3);                  // mfc <= 10 Hz -> real part
    float sre = 0.f, sim = 0.f;

    float tmp_out = 0.f;

    // 32-wide coalesced env prefetch, one block ahead
    float ebuf  = erow[lane];
    float ebufn = (32 + lane < T_) ? erow[32 + lane] : 0.f;

    const int NIT = T_ + 5;
    for (int i = 0; i < NIT; ++i) {
        float prev = __shfl_up_sync(FULL, tmp_out, 1);   // stage j-1 output at t=i-j
        float adv  = __shfl_sync(FULL, tmp_out, 4);      // adaptation output at t=i-5
        float envv = __shfl_sync(FULL, ebuf, i & 31);
        if ((i & 31) == 31) {
            ebuf = ebufn;
            int nidx = i + 1 + 32 + lane;
            ebufn = (nidx < T_) ? erow[nidx] : 0.f;
        }

        // ---- one adaptation loop stage ----
        float tin = (lane == 0) ? fmaxf(envv, C.minlvl) : prev;
        float t1  = tin * rst;
        float e   = __expf(efac * (t1 - 1.0f));
        float lim = __fdividef(fac, 1.0f + e) - offc;
        float to  = (t1 > 1.0f) ? lim : t1;

        int tj = i - lane;
        if (isAd && (unsigned)tj < (unsigned)T_) {
            st = fmaf(a1, st, b0 * to);
            rst = __fdividef(1.0f, st);
            tmp_out = to;
        }

        // ---- modulation resonators (one pipeline stage later) ----
        int tm = i - 5;
        if (isMod && (unsigned)tm < (unsigned)T_) {
            float x   = (adv - C.corr) * C.scale;
            float nre = fmaf(pre, sre, fmaf(-pim, sim, pb0 * x));
            float nim = fmaf(pre, sim, pim * sre);
            sre = nre; sim = nim;
            float o = low ? nre
                          : C.att * sqrtf(fmaf(nre, nre, fmaf(nim, nim, 1e-12f)));
            orow[(size_t)m * T_ + tm] = o;
        }
    }
}

// ---------------- host launch ----------------
extern "C" void kernel_launch(void* const* d_in, const int* in_sizes, int n_in,
                              void* d_out, int out_size) {
    const float* x  = (const float*)d_in[0];
    const float* hp = (const float*)d_in[1];
    const float* me = (const float*)d_in[2];
    const float* gt = (const float*)d_in[3];
    float* out = (float*)d_out;
    (void)in_sizes; (void)n_in; (void)out_size;

    AMConst C;
    const double taus[5] = {0.005, 0.05, 0.129, 0.253, 0.5};
    for (int j = 0; j < 5; ++j) {
        double a1d = exp(-1.0 / (44100.0 * taus[j]));
        float a1f = (float)a1d;
        C.a1[j] = a1f;
        C.b0[j] = 1.0f - a1f;
        double ini = pow(1e-5, pow(2.0, -(double)(j + 1)));
        float inif = (float)ini;
        C.ini[j] = inif;
        double maxv = (1.0 - (double)inif * (double)inif) * 5.0 - 1.0;
        C.fac[j]  = (float)(2.0 * maxv);
        C.efac[j] = (float)(-2.0 / maxv);
        C.off[j]  = (float)(maxv - 1.0);
    }
    double corr = pow(1e-5, 1.0 / 32.0);
    C.corr   = (float)corr;
    C.scale  = (float)(100.0 / (1.0 - corr));
    C.att    = (float)(1.0 / sqrt(2.0));
    C.minlvl = 1e-5f;

    const float mfcf[12] = {2.5f, 5.0f, 10.0f, 16.7f, 27.8f, 46.3f, 77.2f,
                            128.6f, 214.3f, 357.2f, 595.4f, 992.3f};
    for (int m = 0; m < 12; ++m) {
        double mv = (double)mfcf[m];
        double r  = exp(-M_PI * (mv / 2.0) / 44100.0);
        double th = 2.0 * M_PI * mv / 44100.0;
        C.pre[m] = (float)(r * cos(th));
        C.pim[m] = (float)(r * sin(th));
        C.pb0[m] = (float)(1.0 - r);
    }

    hpme_kernel<<<1, 1024>>>(hp, me);
    wlp_kernel<<<1, 256>>>();
    keff_kernel<<<1, 32>>>(gt);

    dim3 blk(128);
    conv1d_kernel<<<dim3(22, B_), blk>>>(x, gt, 0);   // hp+me
    conv1d_kernel<<<dim3(22, BN), blk>>>(x, gt, 1);   // gammatone + rectify
    conv1d_kernel<<<dim3(22, BN), blk>>>(x, gt, 2);   // IHC LP (FIR)

    adapt_mod_kernel<<<BN, 32>>>(out, C);
}